// round 1
// baseline (speedup 1.0000x reference)
#include <cuda_runtime.h>

#define D_MODEL 1024
#define H 16
#define DK 64
#define DV 64
#define BATCH 4
#define SEQ 8192
#define MTOT (BATCH * SEQ)

// ---------------- scratch (device globals: no allocations allowed) ----------
__device__ float g_q[(size_t)MTOT * D_MODEL];                 // 128 MB
__device__ float g_k[(size_t)MTOT * D_MODEL];                 // 128 MB
__device__ float g_v[(size_t)MTOT * D_MODEL];                 // 128 MB
__device__ float g_kv[BATCH * H * DK * DV];                   // 1 MB
__device__ float g_w2t[(size_t)BATCH * D_MODEL * D_MODEL];    // 16 MB

// ---------------- tiled fp32 GEMM: C = A @ B^T + bias -----------------------
// A: [M, 1024] row-major, B: [1024, 1024] row-major (N,K), C: [M, 1024]
#define BM 128
#define BN 128
#define BK 16
#define TM 8
#define TN 8
#define SSTR (BM + 4)   // 132: 16B-aligned fragment loads, low-conflict stores

__device__ __forceinline__ void gemm_abt_bias(
    const float* __restrict__ A,
    const float* __restrict__ Bw,
    const float* __restrict__ bias,
    float* __restrict__ C,
    int bm, int bn)
{
    __shared__ float As[BK][SSTR];
    __shared__ float Bs[BK][SSTR];
    const int tid = threadIdx.x;
    const int tx = tid & 15;
    const int ty = tid >> 4;

    float acc[TM][TN];
#pragma unroll
    for (int i = 0; i < TM; i++)
#pragma unroll
        for (int j = 0; j < TN; j++) acc[i][j] = 0.f;

    for (int k0 = 0; k0 < D_MODEL; k0 += BK) {
#pragma unroll
        for (int u = 0; u < 2; u++) {
            int l   = tid + u * 256;      // 512 float4 loads per operand
            int row = l >> 2;             // 0..127
            int c   = (l & 3) << 2;       // 0,4,8,12
            float4 a = *reinterpret_cast<const float4*>(
                A + (size_t)(bm + row) * D_MODEL + k0 + c);
            As[c + 0][row] = a.x; As[c + 1][row] = a.y;
            As[c + 2][row] = a.z; As[c + 3][row] = a.w;
            float4 b = *reinterpret_cast<const float4*>(
                Bw + (size_t)(bn + row) * D_MODEL + k0 + c);
            Bs[c + 0][row] = b.x; Bs[c + 1][row] = b.y;
            Bs[c + 2][row] = b.z; Bs[c + 3][row] = b.w;
        }
        __syncthreads();
#pragma unroll
        for (int kk = 0; kk < BK; kk++) {
            float ar[TM], br[TN];
            *reinterpret_cast<float4*>(ar)     = *reinterpret_cast<const float4*>(&As[kk][ty * TM]);
            *reinterpret_cast<float4*>(ar + 4) = *reinterpret_cast<const float4*>(&As[kk][ty * TM + 4]);
            *reinterpret_cast<float4*>(br)     = *reinterpret_cast<const float4*>(&Bs[kk][tx * TN]);
            *reinterpret_cast<float4*>(br + 4) = *reinterpret_cast<const float4*>(&Bs[kk][tx * TN + 4]);
#pragma unroll
            for (int i = 0; i < TM; i++)
#pragma unroll
                for (int j = 0; j < TN; j++)
                    acc[i][j] += ar[i] * br[j];
        }
        __syncthreads();
    }

#pragma unroll
    for (int i = 0; i < TM; i++) {
        int row = bm + ty * TM + i;
#pragma unroll
        for (int j4 = 0; j4 < TN; j4 += 4) {
            int col = bn + tx * TN + j4;
            float4 o;
            o.x = acc[i][j4 + 0] + bias[col + 0];
            o.y = acc[i][j4 + 1] + bias[col + 1];
            o.z = acc[i][j4 + 2] + bias[col + 2];
            o.w = acc[i][j4 + 3] + bias[col + 3];
            *reinterpret_cast<float4*>(C + (size_t)row * D_MODEL + col) = o;
        }
    }
}

// ---------------- K1: fused QKV projection (grid.z selects which) -----------
__global__ void __launch_bounds__(256) proj_kernel(
    const float* __restrict__ q_in, const float* __restrict__ k_in,
    const float* __restrict__ v_in,
    const float* __restrict__ Wq, const float* __restrict__ bq,
    const float* __restrict__ Wk, const float* __restrict__ bk,
    const float* __restrict__ Wv, const float* __restrict__ bv)
{
    int which = blockIdx.z;
    const float* A    = (which == 0) ? q_in : (which == 1) ? k_in : v_in;
    const float* W    = (which == 0) ? Wq   : (which == 1) ? Wk   : Wv;
    const float* bias = (which == 0) ? bq   : (which == 1) ? bk   : bv;
    float* C          = (which == 0) ? g_q  : (which == 1) ? g_k  : g_v;
    gemm_abt_bias(A, W, bias, C, blockIdx.y * BM, blockIdx.x * BN);
}

// ---------------- K0: zero kv accumulator ------------------------------------
__global__ void zero_kv_kernel()
{
    int i = blockIdx.x * blockDim.x + threadIdx.x;
    if (i < BATCH * H * DK * DV) g_kv[i] = 0.f;
}

// ---------------- K2: kv[b,h] = sum_n k[b,n,h,:] (x) v[b,n,h,:] --------------
#define NCHUNK 16
#define CHUNK (SEQ / NCHUNK)   // 512

__global__ void __launch_bounds__(256) kv_kernel()
{
    const int bh = blockIdx.x;           // 0..63
    const int chunk = blockIdx.y;        // 0..15
    const int b = bh >> 4, h = bh & 15;

    const float* kbase = g_k + (size_t)b * SEQ * D_MODEL + h * DK;
    const float* vbase = g_v + (size_t)b * SEQ * D_MODEL + h * DK;

    __shared__ float ks[8][64];
    __shared__ float vs[8][64];

    const int tid = threadIdx.x;
    const int tj = tid & 15, ti = tid >> 4;
    float acc[4][4];
#pragma unroll
    for (int i = 0; i < 4; i++)
#pragma unroll
        for (int j = 0; j < 4; j++) acc[i][j] = 0.f;

    const int n0 = chunk * CHUNK;
    for (int nn = n0; nn < n0 + CHUNK; nn += 8) {
        // 256 threads load 256 float4: first 128 -> ks, rest -> vs
        int l   = tid & 127;
        int row = l >> 4;
        int c   = (l & 15) << 2;
        const float* src = (tid < 128) ? kbase : vbase;
        float* dst = (tid < 128) ? &ks[row][c] : &vs[row][c];
        *reinterpret_cast<float4*>(dst) =
            *reinterpret_cast<const float4*>(src + (size_t)(nn + row) * D_MODEL + c);
        __syncthreads();
#pragma unroll
        for (int r = 0; r < 8; r++) {
            float kr[4], vr[4];
            *reinterpret_cast<float4*>(kr) = *reinterpret_cast<const float4*>(&ks[r][ti * 4]);
            *reinterpret_cast<float4*>(vr) = *reinterpret_cast<const float4*>(&vs[r][tj * 4]);
#pragma unroll
            for (int i = 0; i < 4; i++)
#pragma unroll
                for (int j = 0; j < 4; j++)
                    acc[i][j] += kr[i] * vr[j];
        }
        __syncthreads();
    }

    float* kvp = g_kv + (size_t)bh * DK * DV;
#pragma unroll
    for (int i = 0; i < 4; i++)
#pragma unroll
        for (int j = 0; j < 4; j++)
            atomicAdd(&kvp[(ti * 4 + i) * DV + tj * 4 + j], acc[i][j]);
}

// ---------------- K3: xnorm(kv) + fold into W2T[b] ---------------------------
// W2T[b][j][h*64+i] = sum_d kv_n[b,h,i,d] * Wo[j, h*64+d]
__global__ void __launch_bounds__(256) fold_kernel(
    const float* __restrict__ Wo, const float* __restrict__ gamma)
{
    const int bh = blockIdx.x;
    const int b = bh >> 4, h = bh & 15;

    __shared__ float kvn[64][65];
    __shared__ float rn[64];

    const int tid = threadIdx.x;
    const float* kvsrc = g_kv + (size_t)bh * DK * DV;
    for (int l = tid; l < 64 * 64; l += 256)
        kvn[l >> 6][l & 63] = kvsrc[l];
    __syncthreads();

    if (tid < 64) {
        float s = 0.f;
#pragma unroll 8
        for (int d = 0; d < 64; d++) { float x = kvn[tid][d]; s += x * x; }
        rn[tid] = gamma[h] * rsqrtf(s);
    }
    __syncthreads();
    for (int l = tid; l < 64 * 64; l += 256) {
        int i = l >> 6;
        kvn[i][l & 63] *= rn[i];
    }
    __syncthreads();

    const int grp = tid >> 6;   // 0..3
    const int i   = tid & 63;
    float* w2t = g_w2t + (size_t)b * D_MODEL * D_MODEL;
    for (int j = grp; j < D_MODEL; j += 4) {
        const float* wr = Wo + (size_t)j * D_MODEL + h * DK;
        float acc = 0.f;
#pragma unroll 8
        for (int d = 0; d < 64; d++)
            acc += kvn[i][d] * wr[d];
        w2t[(size_t)j * D_MODEL + h * DK + i] = acc;
    }
}

// ---------------- K4: q xnorm in place ---------------------------------------
__global__ void __launch_bounds__(256) qnorm_kernel(const float* __restrict__ gamma)
{
    const size_t rowbase = (size_t)blockIdx.x * D_MODEL;
    const int t = threadIdx.x;
    float4 x = *reinterpret_cast<const float4*>(g_q + rowbase + t * 4);
    float s = x.x * x.x + x.y * x.y + x.z * x.z + x.w * x.w;
    // 16-lane groups == one 64-col head
    s += __shfl_xor_sync(0xffffffffu, s, 1);
    s += __shfl_xor_sync(0xffffffffu, s, 2);
    s += __shfl_xor_sync(0xffffffffu, s, 4);
    s += __shfl_xor_sync(0xffffffffu, s, 8);
    float sc = gamma[t >> 4] * rsqrtf(s);
    x.x *= sc; x.y *= sc; x.z *= sc; x.w *= sc;
    *reinterpret_cast<float4*>(g_q + rowbase + t * 4) = x;
}

// ---------------- K5: out[b] = q_n[b] @ W2T[b]^T + bo ------------------------
__global__ void __launch_bounds__(256) out_kernel(
    const float* __restrict__ bo, float* __restrict__ out)
{
    const int b = blockIdx.z;
    gemm_abt_bias(g_q   + (size_t)b * SEQ * D_MODEL,
                  g_w2t + (size_t)b * D_MODEL * D_MODEL,
                  bo,
                  out   + (size_t)b * SEQ * D_MODEL,
                  blockIdx.y * BM, blockIdx.x * BN);
}

// ---------------- launch ------------------------------------------------------
extern "C" void kernel_launch(void* const* d_in, const int* in_sizes, int n_in,
                              void* d_out, int out_size)
{
    const float* queries = (const float*)d_in[0];
    const float* keys    = (const float*)d_in[1];
    const float* values  = (const float*)d_in[2];
    const float* Wq = (const float*)d_in[3];
    const float* bq = (const float*)d_in[4];
    const float* Wk = (const float*)d_in[5];
    const float* bk = (const float*)d_in[6];
    const float* Wv = (const float*)d_in[7];
    const float* bv = (const float*)d_in[8];
    const float* Wo = (const float*)d_in[9];
    const float* bo = (const float*)d_in[10];
    const float* gamma = (const float*)d_in[11];
    float* out = (float*)d_out;

    zero_kv_kernel<<<(BATCH * H * DK * DV + 255) / 256, 256>>>();

    dim3 gproj(D_MODEL / BN, MTOT / BM, 3);
    proj_kernel<<<gproj, 256>>>(queries, keys, values, Wq, bq, Wk, bk, Wv, bv);

    kv_kernel<<<dim3(BATCH * H, NCHUNK), 256>>>();
    fold_kernel<<<BATCH * H, 256>>>(Wo, gamma);
    qnorm_kernel<<<MTOT, 256>>>(gamma);

    dim3 gout(D_MODEL / BN, SEQ / BM, BATCH);
    out_kernel<<<gout, 256>>>(bo, out);
}